// round 16
// baseline (speedup 1.0000x reference)
#include <cuda_runtime.h>
#include <cuda_fp16.h>

#define NV 100000
#define NE 1600000
#define CSCP 2400000            // NE + 8*NV (padded CSC)
#define ZD 192
#define HD 512
#define OD 64
#define EPS 1e-5f

typedef unsigned long long ull;

__device__ __forceinline__ unsigned smem_u32(const void* p){
    unsigned a;
    asm("{ .reg .u64 t; cvta.to.shared.u64 t, %1; cvt.u32.u64 %0, t; }" : "=r"(a) : "l"(p));
    return a;
}

// upper-triangle 16x16 tile list for S (12x12 tiles, i<=j): 78 tiles
__constant__ unsigned char c_i16[78] = {
    0,0,0,0,0,0,0,0,0,0,0,0,
    1,1,1,1,1,1,1,1,1,1,1,
    2,2,2,2,2,2,2,2,2,2,
    3,3,3,3,3,3,3,3,3,
    4,4,4,4,4,4,4,4,
    5,5,5,5,5,5,5,
    6,6,6,6,6,6,
    7,7,7,7,7,
    8,8,8,8,
    9,9,9,
    10,10,
    11};
__constant__ unsigned char c_j16[78] = {
    0,1,2,3,4,5,6,7,8,9,10,11,
    1,2,3,4,5,6,7,8,9,10,11,
    2,3,4,5,6,7,8,9,10,11,
    3,4,5,6,7,8,9,10,11,
    4,5,6,7,8,9,10,11,
    5,6,7,8,9,10,11,
    6,7,8,9,10,11,
    7,8,9,10,11,
    8,9,10,11,
    9,10,11,
    10,11,
    11};

// scratch (no allocations allowed)
__device__ int   g_deg[NV];
__device__ int   g_off[NV];
__device__ int   g_csc[CSCP];
__device__ float g_norm[NV];
__device__ uint2 g_tA16[(NV+1)*16];    // fp16 t, 64 halves/row; row NV = zeros (pad target)
__device__ uint2 g_tB16[(NV+1)*16];
__device__ uint2 g_H16[(size_t)NV*48]; // fp16 H: 192 halves/row
__device__ float g_S[ZD*ZD];           // Gram (upper triangle authoritative)
__device__ float g_cs[ZD];             // column sums
__device__ float g_M[HD*ZD];           // folded weights (atomically accumulated)
__device__ float g_cv[HD];             // folded bias
__device__ float g_av[HD];             // q*gamma*invstd
__device__ float g_dt[HD];             // per-channel const
__device__ __half g_V16[ZD*OD];        // fused matrix, fp16
__device__ float g_dc[OD];
__device__ int   g_bsum[128];

// zero/init; CSC filled with dummy index NV via int4
__global__ void k_zero(){
    int i = blockIdx.x*256 + threadIdx.x;
    if (i < CSCP/4) ((int4*)g_csc)[i] = make_int4(NV,NV,NV,NV);
    if (i < NV)    g_deg[i] = 0;
    if (i < HD*ZD) g_M[i]   = 0.f;
    if (i < ZD*ZD) g_S[i]   = 0.f;
    if (i < ZD)    g_cs[i]  = 0.f;
    if (i < 16){
        g_tA16[NV*16 + i] = make_uint2(0u,0u);
        g_tB16[NV*16 + i] = make_uint2(0u,0u);
    }
}

// folded-weight GEMM: grid = 8 ko-tiles x 3 j x 8 K-chunks = 192 blocks
__global__ void __launch_bounds__(256) k_wgemm(const float* __restrict__ fcW,
                          const float* __restrict__ W0, const float* __restrict__ W1,
                          const float* __restrict__ W2){
    __shared__ float As[64][68];
    __shared__ float Bs[64][64];
    int b = blockIdx.x;
    int mt = b & 7;
    int j  = (b >> 3) % 3;
    int kc = b / 24;
    int ko0 = mt << 6, k0 = kc << 6;
    const float* W = (j==0)?W0:((j==1)?W1:W2);
    int tid = threadIdx.x;
    int ty = tid >> 4, tx = tid & 15;

    for (int t = tid; t < 1024; t += 256){
        int r = t >> 4, c4 = (t & 15) << 2;
        float4 v = __ldg((const float4*)(fcW + (size_t)(ko0 + r)*1536 + j*512 + k0 + c4));
        As[r][c4] = v.x; As[r][c4+1] = v.y; As[r][c4+2] = v.z; As[r][c4+3] = v.w;
    }
    for (int t = tid; t < 1024; t += 256){
        int r = t >> 4, c4 = (t & 15) << 2;
        float4 v = __ldg((const float4*)(W + (size_t)(k0 + r)*64 + c4));
        *(float4*)&Bs[r][c4] = v;
    }
    __syncthreads();

    float acc[4][4] = {};
    #pragma unroll 8
    for (int k = 0; k < 64; k++){
        float a0 = As[ty*4+0][k];
        float a1 = As[ty*4+1][k];
        float a2 = As[ty*4+2][k];
        float a3 = As[ty*4+3][k];
        float4 bv = *(const float4*)&Bs[k][tx*4];
        acc[0][0]=fmaf(a0,bv.x,acc[0][0]); acc[0][1]=fmaf(a0,bv.y,acc[0][1]);
        acc[0][2]=fmaf(a0,bv.z,acc[0][2]); acc[0][3]=fmaf(a0,bv.w,acc[0][3]);
        acc[1][0]=fmaf(a1,bv.x,acc[1][0]); acc[1][1]=fmaf(a1,bv.y,acc[1][1]);
        acc[1][2]=fmaf(a1,bv.z,acc[1][2]); acc[1][3]=fmaf(a1,bv.w,acc[1][3]);
        acc[2][0]=fmaf(a2,bv.x,acc[2][0]); acc[2][1]=fmaf(a2,bv.y,acc[2][1]);
        acc[2][2]=fmaf(a2,bv.z,acc[2][2]); acc[2][3]=fmaf(a2,bv.w,acc[2][3]);
        acc[3][0]=fmaf(a3,bv.x,acc[3][0]); acc[3][1]=fmaf(a3,bv.y,acc[3][1]);
        acc[3][2]=fmaf(a3,bv.z,acc[3][2]); acc[3][3]=fmaf(a3,bv.w,acc[3][3]);
    }
    #pragma unroll
    for (int r = 0; r < 4; r++){
        int ko = ko0 + ty*4 + r;
        #pragma unroll
        for (int c = 0; c < 4; c++)
            atomicAdd(&g_M[(size_t)ko*ZD + j*64 + tx*4 + c], acc[r][c]);
    }
}

// bias fold: warp per channel
__global__ void k_wbias(const float* __restrict__ fcW,
                        const float* __restrict__ b0, const float* __restrict__ b1,
                        const float* __restrict__ b2, const float* __restrict__ fcb){
    int w = (blockIdx.x*256 + threadIdx.x) >> 5;
    int lane = threadIdx.x & 31;
    if (w >= HD) return;
    const float* fr = fcW + (size_t)w*1536;
    float s = 0.f;
    #pragma unroll 4
    for (int h = lane; h < HD; h += 32)
        s += fr[h]*b0[h] + fr[512+h]*b1[h] + fr[1024+h]*b2[h];
    #pragma unroll
    for (int o=16;o;o>>=1) s += __shfl_xor_sync(0xffffffffu, s, o);
    if (lane == 0) g_cv[w] = s + fcb[w];
}

__global__ void k_deg(const int* __restrict__ dst){
    int e = blockIdx.x*256 + threadIdx.x;
    if (e < NE) atomicAdd(&g_deg[dst[e]], 1);
}

// scan of PADDED degrees ((d+7)&~7) -> 8-aligned slot starts
__global__ void k_scan1(){
    __shared__ int sh[1024];
    int t = threadIdx.x, i = blockIdx.x*1024 + t;
    int d = (i < NV) ? g_deg[i] : 0;
    int v = (d + 7) & ~7;
    sh[t] = v; __syncthreads();
    for (int off=1; off<1024; off<<=1){
        int x = (t >= off) ? sh[t-off] : 0; __syncthreads();
        sh[t] += x; __syncthreads();
    }
    if (i < NV) g_off[i] = sh[t] - v;
    if (t == 1023) g_bsum[blockIdx.x] = sh[1023];
}

// finalize slot starts/norm AND scale feats -> tA16 (fp16); inline block-sum prefix
__global__ void k_scan3t0(const float* __restrict__ feats){
    __shared__ float snorm[256];
    __shared__ int sboff;
    int t = threadIdx.x;
    int i = blockIdx.x*256 + t;
    int chunk = blockIdx.x >> 2;
    if (t < 32){
        int s = 0;
        for (int j = t; j < chunk; j += 32) s += g_bsum[j];
        #pragma unroll
        for (int o=16;o;o>>=1) s += __shfl_xor_sync(0xffffffffu, s, o);
        if (t == 0) sboff = s;
    }
    __syncthreads();
    if (i < NV){
        g_off[i] += sboff;
        int d = g_deg[i];
        float nv = rsqrtf((float)(d > 1 ? d : 1));
        g_norm[i] = nv;
        snorm[t]  = nv;
    }
    __syncthreads();
    int base4 = blockIdx.x*256*16;
    for (int tt = t; tt < 256*16; tt += 256){
        int r = tt >> 4;
        if (blockIdx.x*256 + r < NV){
            float4 v = __ldg(((const float4*)feats) + base4 + tt);
            float nv = snorm[r];
            uint2 o;
            *(__half2*)&o.x = __floats2half2_rn(v.x*nv, v.y*nv);
            *(__half2*)&o.y = __floats2half2_rn(v.z*nv, v.w*nv);
            g_tA16[base4 + tt] = o;
        }
    }
}

// place edges; cursor is g_off itself
__global__ void k_place(const int* __restrict__ src, const int* __restrict__ dst){
    int e = blockIdx.x*256 + threadIdx.x;
    if (e < NE){
        int p = atomicAdd(&g_off[dst[e]], 1);
        g_csc[p] = src[e];
    }
}

// hop: warp per node; uniform ceil(deg/8) iters
__global__ void k_hop(int sel, int coff16, int wt){
    int gw   = (blockIdx.x*blockDim.x + threadIdx.x) >> 5;
    int lane = threadIdx.x & 31;
    if (gw >= NV) return;
    const uint2* tin  = sel ? g_tB16 : g_tA16;
    uint2*       tout = sel ? g_tA16 : g_tB16;
    int dv = g_deg[gw];
    int s  = g_off[gw] - dv;
    int niter = (dv + 7) >> 3;
    int half = lane >> 4;
    int c4   = lane & 15;
    float ax=0.f, ay=0.f, az=0.f, aw=0.f;
    const int* base = g_csc + s + half*4;
    for (int it = 0; it < niter; it++){
        int4 u = *(const int4*)(base + it*8);
        uint2 w0 = __ldg(&tin[u.x*16 + c4]);
        uint2 w1 = __ldg(&tin[u.y*16 + c4]);
        uint2 w2 = __ldg(&tin[u.z*16 + c4]);
        uint2 w3 = __ldg(&tin[u.w*16 + c4]);
        float2 a0 = __half22float2(*(__half2*)&w0.x), b0 = __half22float2(*(__half2*)&w0.y);
        float2 a1 = __half22float2(*(__half2*)&w1.x), b1 = __half22float2(*(__half2*)&w1.y);
        float2 a2 = __half22float2(*(__half2*)&w2.x), b2 = __half22float2(*(__half2*)&w2.y);
        float2 a3 = __half22float2(*(__half2*)&w3.x), b3 = __half22float2(*(__half2*)&w3.y);
        ax += (a0.x + a1.x) + (a2.x + a3.x);
        ay += (a0.y + a1.y) + (a2.y + a3.y);
        az += (b0.x + b1.x) + (b2.x + b3.x);
        aw += (b0.y + b1.y) + (b2.y + b3.y);
    }
    ax += __shfl_xor_sync(0xffffffffu, ax, 16);
    ay += __shfl_xor_sync(0xffffffffu, ay, 16);
    az += __shfl_xor_sync(0xffffffffu, az, 16);
    aw += __shfl_xor_sync(0xffffffffu, aw, 16);
    if (half == 0){
        float nv = g_norm[gw];
        float hx = ax*nv, hy = ay*nv, hz = az*nv, hw = aw*nv;
        uint2 hh;
        *(__half2*)&hh.x = __floats2half2_rn(hx, hy);
        *(__half2*)&hh.y = __floats2half2_rn(hz, hw);
        g_H16[(size_t)gw*48 + coff16 + c4] = hh;
        if (wt){
            uint2 o;
            *(__half2*)&o.x = __floats2half2_rn(hx*nv, hy*nv);
            *(__half2*)&o.y = __floats2half2_rn(hz*nv, hw*nv);
            tout[gw*16 + c4] = o;
        }
    }
}

// HMMA Gram: S = Z^T Z via mma.m16n8k16; 78 upper tiles, 16 warps x <=5 tiles
__global__ void __launch_bounds__(512,1) k_gram(){
    __shared__ __align__(16) __half zs16[64*200];
    int tid = threadIdx.x;
    int w = tid >> 5, lane = tid & 31;
    int nt = (w < 14) ? 5 : 4;                 // 78 = 14*5 + 2*4
    int ti[5], tj[5];
    #pragma unroll
    for (int k=0;k<5;k++){
        int t = w + (k<<4);
        if (t < 78){ ti[k] = ((int)c_i16[t])<<4; tj[k] = ((int)c_j16[t])<<4; }
        else       { ti[k] = 0;                 tj[k] = 0; }
    }
    float d[5][8];
    #pragma unroll
    for (int k=0;k<5;k++){
        #pragma unroll
        for (int m=0;m<8;m++) d[k][m] = 0.f;
    }
    float csacc = 0.f;
    unsigned zbase = smem_u32(zs16);
    int r8  = lane & 7;
    int mat = lane >> 3;
    int aK = r8 + ((mat & 2) ? 8 : 0);
    int aC = (mat & 1) ? 8 : 0;
    int bK = r8 + ((mat & 1) ? 8 : 0);
    int bC = (mat & 2) ? 8 : 0;

    int ntile = (NV + 63) >> 6;
    for (int tile = blockIdx.x; tile < ntile; tile += gridDim.x){
        int r0 = tile << 6;
        int valid = NV - r0; if (valid > 64) valid = 64;
        for (int t = tid; t < 64*48; t += 512){
            int r = t / 48, c = t - r*48;
            uint2 wv = (r < valid) ? __ldg(&g_H16[(size_t)(r0+r)*48 + c])
                                   : make_uint2(0u,0u);
            *(uint2*)&zs16[r*200 + c*4] = wv;
        }
        __syncthreads();
        #pragma unroll
        for (int ks = 0; ks < 4; ks++){
            int k0 = ks << 4;
            #pragma unroll
            for (int k=0;k<5;k++){
                if (k >= nt) break;
                unsigned aaddr = zbase + (unsigned)(((k0 + aK)*200 + ti[k] + aC) << 1);
                unsigned baddr = zbase + (unsigned)(((k0 + bK)*200 + tj[k] + bC) << 1);
                unsigned a0,a1,a2,a3,b0,b1,b2,b3;
                asm volatile("ldmatrix.sync.aligned.m8n8.x4.trans.shared.b16 {%0,%1,%2,%3}, [%4];"
                    : "=r"(a0),"=r"(a1),"=r"(a2),"=r"(a3) : "r"(aaddr));
                asm volatile("ldmatrix.sync.aligned.m8n8.x4.trans.shared.b16 {%0,%1,%2,%3}, [%4];"
                    : "=r"(b0),"=r"(b1),"=r"(b2),"=r"(b3) : "r"(baddr));
                asm volatile("mma.sync.aligned.m16n8k16.row.col.f32.f16.f16.f32 "
                    "{%0,%1,%2,%3}, {%4,%5,%6,%7}, {%8,%9}, {%0,%1,%2,%3};"
                    : "+f"(d[k][0]),"+f"(d[k][1]),"+f"(d[k][2]),"+f"(d[k][3])
                    : "r"(a0),"r"(a1),"r"(a2),"r"(a3), "r"(b0),"r"(b1));
                asm volatile("mma.sync.aligned.m16n8k16.row.col.f32.f16.f16.f32 "
                    "{%0,%1,%2,%3}, {%4,%5,%6,%7}, {%8,%9}, {%0,%1,%2,%3};"
                    : "+f"(d[k][4]),"+f"(d[k][5]),"+f"(d[k][6]),"+f"(d[k][7])
                    : "r"(a0),"r"(a1),"r"(a2),"r"(a3), "r"(b2),"r"(b3));
            }
        }
        if (tid < ZD){
            float s = 0.f;
            #pragma unroll 8
            for (int r=0; r<64; r++) s += __half2float(zs16[r*200 + tid]);
            csacc += s;
        }
        __syncthreads();
    }
    int g = lane >> 2, tq = lane & 3;
    #pragma unroll
    for (int k=0;k<5;k++){
        if (k >= nt) break;
        int i0 = ti[k], j0 = tj[k];
        atomicAdd(&g_S[(i0+g  )*ZD + j0   + 2*tq    ], d[k][0]);
        atomicAdd(&g_S[(i0+g  )*ZD + j0   + 2*tq + 1], d[k][1]);
        atomicAdd(&g_S[(i0+g+8)*ZD + j0   + 2*tq    ], d[k][2]);
        atomicAdd(&g_S[(i0+g+8)*ZD + j0   + 2*tq + 1], d[k][3]);
        atomicAdd(&g_S[(i0+g  )*ZD + j0+8 + 2*tq    ], d[k][4]);
        atomicAdd(&g_S[(i0+g  )*ZD + j0+8 + 2*tq + 1], d[k][5]);
        atomicAdd(&g_S[(i0+g+8)*ZD + j0+8 + 2*tq    ], d[k][6]);
        atomicAdd(&g_S[(i0+g+8)*ZD + j0+8 + 2*tq + 1], d[k][7]);
    }
    if (tid < ZD) atomicAdd(&g_cs[tid], csacc);
}

// BN stats per output channel (reads upper triangle of S); fold with q
__global__ void k_stats(const float* __restrict__ gamma, const float* __restrict__ beta,
                        const float* __restrict__ q){
    __shared__ float m[ZD], r1[ZD], r2[ZD];
    int ko = blockIdx.x, t = threadIdx.x;
    m[t] = g_M[ko*ZD + t];
    __syncthreads();
    float w = 0.f;
    #pragma unroll 4
    for (int j=0;j<ZD;j++){
        float sv = (j >= t) ? g_S[t*ZD + j] : g_S[j*ZD + t];
        w = fmaf(sv, m[j], w);
    }
    r1[t] = m[t]*w;
    r2[t] = m[t]*g_cs[t];
    __syncthreads();
    for (int s=96; s>=3; s>>=1){
        if (t < s){ r1[t] += r1[t+s]; r2[t] += r2[t+s]; }
        __syncthreads();
    }
    if (t == 0){
        float qf  = r1[0]+r1[1]+r1[2];
        float mz  = (r2[0]+r2[1]+r2[2]) * (1.0f/NV);
        float var = qf*(1.0f/NV) - mz*mz;
        float c   = g_cv[ko];
        float inv = rsqrtf(var + EPS);
        float sc  = gamma[ko]*inv;
        float tsh = beta[ko] - (mz + c)*sc;
        float qk  = q[ko >> 6];
        g_av[ko] = qk*sc;
        g_dt[ko] = qk*(sc*c + tsh);
    }
}

// fuse BN scale + q into V16 (fp16) and dconst
__global__ void k_vk(){
    int idx = blockIdx.x*256 + threadIdx.x;
    if (idx < ZD*OD){
        int i = idx >> 6, o = idx & 63;
        float s = 0.f;
        #pragma unroll
        for (int k=0;k<8;k++){ int ko = k*64+o; s = fmaf(g_av[ko], g_M[ko*ZD + i], s); }
        g_V16[idx] = __float2half(s);
    } else if (idx < ZD*OD + OD){
        int o = idx - ZD*OD;
        float s = 0.f;
        #pragma unroll
        for (int k=0;k<8;k++) s += g_dt[k*64+o];
        g_dc[o] = s;
    }
}

// HMMA out = H @ V^T + dconst ; 128 rows/block, 8 warps
__global__ void __launch_bounds__(256) k_out(float* __restrict__ out){
    __shared__ __align__(16) __half Hs[128*24];
    __shared__ __align__(16) __half Vs[16*72];
    __shared__ float dcs[OD];
    int tid = threadIdx.x, w = tid >> 5, lane = tid & 31;
    int r0 = blockIdx.x * 128;
    int valid = NV - r0; if (valid > 128) valid = 128;
    if (tid < OD) dcs[tid] = g_dc[tid];

    float d[8][4];
    #pragma unroll
    for (int n=0;n<8;n++){
        #pragma unroll
        for (int m=0;m<4;m++) d[n][m] = 0.f;
    }
    unsigned hb = smem_u32(Hs), vb = smem_u32(Vs);
    int aRow = lane & 15, aCol = (lane >> 4) << 3;
    int r8 = lane & 7, mat = lane >> 3;
    int bK = r8 + ((mat & 1) ? 8 : 0);
    int bC = (mat & 2) ? 8 : 0;
    unsigned aaddr = hb + ((unsigned)((w*16 + aRow)*24 + aCol) << 1);

    for (int kc = 0; kc < 12; kc++){
        for (int t = tid; t < 512; t += 256){
            int r = t >> 2, q = t & 3;
            uint2 v = (r < valid) ? __ldg(&g_H16[(size_t)(r0+r)*48 + kc*4 + q])
                                  : make_uint2(0u,0u);
            *(uint2*)&Hs[r*24 + q*4] = v;
        }
        {
            int r = tid >> 4, q = tid & 15;
            uint2 v = *(const uint2*)&g_V16[(kc*16 + r)*64 + q*4];
            *(uint2*)&Vs[r*72 + q*4] = v;
        }
        __syncthreads();
        unsigned a0,a1,a2,a3;
        asm volatile("ldmatrix.sync.aligned.m8n8.x4.shared.b16 {%0,%1,%2,%3}, [%4];"
            : "=r"(a0),"=r"(a1),"=r"(a2),"=r"(a3) : "r"(aaddr));
        #pragma unroll
        for (int jb = 0; jb < 4; jb++){
            unsigned baddr = vb + ((unsigned)(bK*72 + jb*16 + bC) << 1);
            unsigned b0,b1,b2,b3;
            asm volatile("ldmatrix.sync.aligned.m8n8.x4.trans.shared.b16 {%0,%1,%2,%3}, [%4];"
                : "=r"(b0),"=r"(b1),"=r"(b2),"=r"(b3) : "r"(baddr));
            asm volatile("mma.sync.aligned.m16n8k16.row.col.f32.f16.f16.f32 "
                "{%0,%1,%2,%3}, {%4,%5,%6,%7}, {%8,%9}, {%0,%1,%2,%3};"
                : "+f"(d[jb*2][0]),"+f"(d[jb*2][1]),"+f"(d[jb*2][2]),"+f"(d[jb*2][3])
                : "r"(a0),"r"(a1),"r"(a2),"r"(a3), "r"(b0),"r"(b1));
            asm volatile("mma.sync.aligned.m16n8k16.row.col.f32.f16.f16.f32 "
                "{%0,%1,%2,%3}, {%4,%5,%6,%7}, {%8,%9}, {%0,%1,%2,%3};"
                : "+f"(d[jb*2+1][0]),"+f"(d[jb*2+1][1]),"+f"(d[jb*2+1][2]),"+f"(d[jb*2+1][3])
                : "r"(a0),"r"(a1),"r"(a2),"r"(a3), "r"(b2),"r"(b3));
        }
        __syncthreads();
    }
    int g = lane >> 2, tq = lane & 3;
    #pragma unroll
    for (int n = 0; n < 8; n++){
        int col = (n >> 1)*16 + (n & 1)*8 + 2*tq;
        int row = r0 + w*16 + g;
        if (row < NV){
            float2 p = make_float2(d[n][0] + dcs[col], d[n][1] + dcs[col+1]);
            *(float2*)&out[(size_t)row*64 + col] = p;
        }
        row += 8;
        if (row < NV){
            float2 p = make_float2(d[n][2] + dcs[col], d[n][3] + dcs[col+1]);
            *(float2*)&out[(size_t)row*64 + col] = p;
        }
    }
}

extern "C" void kernel_launch(void* const* d_in, const int* in_sizes, int n_in,
                              void* d_out, int out_size){
    const float* feats = (const float*)d_in[0];
    const int*   src   = (const int*)  d_in[1];
    const int*   dst   = (const int*)  d_in[2];
    const float* W0    = (const float*)d_in[3];
    const float* b0    = (const float*)d_in[4];
    const float* W1    = (const float*)d_in[5];
    const float* b1    = (const float*)d_in[6];
    const float* W2    = (const float*)d_in[7];
    const float* b2    = (const float*)d_in[8];
    const float* fcW   = (const float*)d_in[9];
    const float* fcb   = (const float*)d_in[10];
    const float* gamma = (const float*)d_in[11];
    const float* beta  = (const float*)d_in[12];
    const float* q     = (const float*)d_in[13];
    float* out = (float*)d_out;

    k_zero   <<<2344, 256>>>();                                   // #1
    k_wgemm  <<<192, 256>>>(fcW, W0, W1, W2);                     // #2
    k_wbias  <<<64, 256>>>(fcW, b0, b1, b2, fcb);                 // #3
    k_deg    <<<6250, 256>>>(dst);                                // #4  <- profiled slot
    k_scan1  <<<98, 1024>>>();                                    // #5
    k_scan3t0<<<391, 256>>>(feats);                               // #6
    k_place  <<<6250, 256>>>(src, dst);                           // #7
    // hops duplicated (idempotent): dur delta vs R15 measures hop1+hop2+hop3
    k_hop    <<<12500, 256>>>(0, 0,  1);                          // #8
    k_hop    <<<12500, 256>>>(0, 0,  1);                          // #9  dup
    k_hop    <<<12500, 256>>>(1, 16, 1);                          // #10
    k_hop    <<<12500, 256>>>(1, 16, 1);                          // #11 dup
    k_hop    <<<12500, 256>>>(0, 32, 0);                          // #12
    k_hop    <<<12500, 256>>>(0, 32, 0);                          // #13 dup
    k_gram   <<<148, 512>>>();                                    // #14
    k_stats  <<<512, 192>>>(gamma, beta, q);                      // #15
    k_vk     <<<49, 256>>>();                                     // #16
    k_out    <<<782, 256>>>(out);                                 // #17
}